// round 8
// baseline (speedup 1.0000x reference)
#include <cuda_runtime.h>

// InterConv: B=2048, F=39, E=64, C=64, P=741
// out[b, c*P + p] = relu( U[c][ii[p]] + V[c][jj[p]] ),  U = x@Wi^T + bias, V = x@Wj^T
//
// 43.0 KB smem, <=51 regs -> 5 CTAs/SM (40 warps).
// smem (floats):
//   phase 0/1: xs [0,2560)  W swizzled [2560,10752)  (Wi 4096 + Wj 4096, stride 64,
//              16B-unit index = e4 ^ (c&7) -> conflict-free LDS.128 both ways)
//   phase 2:   Uc [0,2624)  Vc [2624,5248)  tab [5248,5992)   (overlay, W/xs dead)
//
// Phase 2: row-pairing (p0(c)=27c mod 32 == p0(c+32)); 22-entry tab window cached
// in registers per pair; 3 L1 wavefronts per 32 outputs (u, v, store).

#define FN 39
#define EN 64
#define CN 64
#define PN 741            // 39*38/2
#define OUTB (CN * PN)    // 47424 floats per batch
#define THREADS 256

#define XS_OFF  0
#define W_OFF   2560
#define UC_OFF  0
#define VC_OFF  2624
#define TAB_OFF 5248
#define SMEM_FLOATS 10752
#define SMEM_BYTES  (SMEM_FLOATS * 4)   // 43008

extern __shared__ float smem[];

__global__ void __launch_bounds__(THREADS, 5)
interconv_kernel(const float* __restrict__ x,
                 const float* __restrict__ W,
                 const float* __restrict__ bias,
                 float* __restrict__ out)
{
    const int tid = threadIdx.x;
    const long long b = blockIdx.x;

    // ---- Phase 0: stage x and W (float4, W swizzled) ---------------------
    {
        float4* xs4 = (float4*)(smem + XS_OFF);
        const float4* xb4 = (const float4*)(x + b * (long long)(FN * EN));
        #pragma unroll
        for (int it = 0; it < 3; it++) {
            int idx = tid + it * THREADS;
            if (idx < (FN * EN) / 4) xs4[idx] = xb4[idx];
        }
        if (tid < EN)                              // zero pad row f=39
            smem[XS_OFF + FN * EN + tid] = 0.f;

        // W gmem: [c][128] floats (k=0 -> Wi, k=1 -> Wj)
        // smem: Wi4[c*16 + (e4 ^ (c&7))], Wj4 likewise at +1024 float4
        float4* Wi4 = (float4*)(smem + W_OFF);
        float4* Wj4 = Wi4 + 1024;
        const float4* Wg4 = (const float4*)W;
        #pragma unroll
        for (int it = 0; it < 8; it++) {
            int idx = tid + it * THREADS;          // 2048 float4 total
            int c = idx >> 5, q = idx & 31;
            int s = c & 7;
            float4 w = Wg4[idx];
            if (q < 16) Wi4[c * 16 + (q ^ s)] = w;
            else        Wj4[c * 16 + ((q - 16) ^ s)] = w;
        }
    }
    __syncthreads();

    // ---- Phase 1: U = x @ Wi^T + b, V = x @ Wj^T  (scalar f32) ----------
    const int c  = tid & 63;
    const int fg = tid >> 6;

    float au[10], av[10];
    #pragma unroll
    for (int k = 0; k < 10; k++) { au[k] = 0.f; av[k] = 0.f; }

    {
        const float4* xs4 = (const float4*)(smem + XS_OFF);   // [f][16]
        const float4* Wi4 = (const float4*)(smem + W_OFF);
        const float4* Wj4 = Wi4 + 1024;
        const int s = c & 7;

        #pragma unroll
        for (int e4 = 0; e4 < 16; e4++) {
            float4 wi = Wi4[c * 16 + (e4 ^ s)];
            float4 wj = Wj4[c * 16 + (e4 ^ s)];
            #pragma unroll
            for (int k = 0; k < 10; k++) {
                float4 xv = xs4[(fg + 4 * k) * 16 + e4];      // f=39 row is zeros
                au[k] += xv.x * wi.x + xv.y * wi.y + xv.z * wi.z + xv.w * wi.w;
                av[k] += xv.x * wj.x + xv.y * wj.y + xv.z * wj.z + xv.w * wj.w;
            }
        }
    }
    __syncthreads();   // all xs/W reads done; safe to overlay

    // ---- Phase 1b: write Uc/Vc (transposed, stride 41) + build tab ------
    float* Uc = smem + UC_OFF;                // [c][41]
    float* Vc = smem + VC_OFF;                // [c][41]
    unsigned* tab = (unsigned*)(smem + TAB_OFF);

    {
        const float bc = __ldg(bias + c);
        #pragma unroll
        for (int k = 0; k < 10; k++) {
            int f = fg + 4 * k;               // f<=39; f=39 lands in row pad
            Uc[c * 41 + f] = au[k] + bc;      // bias folded into U
            Vc[c * 41 + f] = av[k];
        }
        // pair table: np.triu_indices(F,1) row-major; byte offsets (i*4 | j*4<<16)
        for (int p = tid; p < PN; p += THREADS) {
            int i = 0, rem = p;
            while (rem >= FN - 1 - i) { rem -= FN - 1 - i; i++; }
            int j = i + 1 + rem;
            tab[p] = (unsigned)(i * 4) | ((unsigned)(j * 4) << 16);
        }
    }
    __syncthreads();

    // ---- Phase 2: expansion + relu, paired rows, register-cached tab -----
    const int lane = tid & 31;
    const int wrp  = tid >> 5;
    float* outb = out + b * (long long)OUTB;

    #pragma unroll 1
    for (int k = 0; k < 4; k++) {
        const int r  = wrp * 4 + k;           // rows r and r+32 share p0
        const int p0 = (27 * r) & 31;

        // preload the 22-entry aligned tab window into registers
        unsigned tw[22];
        {
            const unsigned* tb = tab + p0 + lane;
            #pragma unroll
            for (int it = 0; it < 22; it++) tw[it] = tb[it * 32];
        }

        #pragma unroll
        for (int h = 0; h < 2; h++) {
            const int gc = r + 32 * h;
            const char* bu = (const char*)(Uc + gc * 41);
            const char* bv = (const char*)(Vc + gc * 41);
            float* po = outb + gc * PN;

            // head: p in [0, p0)
            if (lane < p0) {
                unsigned t = tab[lane];
                float u = *(const float*)(bu + (t & 0xFFFFu));
                float v = *(const float*)(bv + (t >> 16));
                __stcs(po + lane, fmaxf(u + v, 0.f));
            }

            // main: 22 full warp-iterations, register tab, 128B-aligned stores
            float* po2 = po + p0;
            #pragma unroll
            for (int it = 0; it < 22; it++) {
                unsigned t = tw[it];
                float u = *(const float*)(bu + (t & 0xFFFFu));
                float v = *(const float*)(bv + (t >> 16));
                __stcs(po2 + it * 32 + lane, fmaxf(u + v, 0.f));
            }

            // tail: p in [p0+704, 741)
            int p = p0 + 704 + lane;
            if (p < PN) {
                unsigned t = tab[p];
                float u = *(const float*)(bu + (t & 0xFFFFu));
                float v = *(const float*)(bv + (t >> 16));
                __stcs(po + p, fmaxf(u + v, 0.f));
            }
            p += 32;
            if (p < PN) {
                unsigned t = tab[p];
                float u = *(const float*)(bu + (t & 0xFFFFu));
                float v = *(const float*)(bv + (t >> 16));
                __stcs(po + p, fmaxf(u + v, 0.f));
            }
        }
    }
}

extern "C" void kernel_launch(void* const* d_in, const int* in_sizes, int n_in,
                              void* d_out, int out_size)
{
    const float* x    = (const float*)d_in[0];
    const float* W    = (const float*)d_in[1];
    const float* bias = (const float*)d_in[2];
    float* out = (float*)d_out;

    const int B = in_sizes[0] / (FN * EN);   // 2048

    cudaFuncSetAttribute(interconv_kernel,
                         cudaFuncAttributeMaxDynamicSharedMemorySize, SMEM_BYTES);
    interconv_kernel<<<B, THREADS, SMEM_BYTES>>>(x, W, bias, out);
}

// round 9
// speedup vs baseline: 1.1443x; 1.1443x over previous
#include <cuda_runtime.h>

// InterConv: B=2048, F=39, E=64, C=64, P=741
// out[b, c*P + p] = relu( U[c][ii[p]] + V[c][jj[p]] ),  U = x@Wi^T + bias, V = x@Wj^T
//
// smem (floats), 45.7 KB -> 4 CTAs/SM:
//   phase 0/1: xs [0,2720)  rows padded to 17 float4 units (f*17+e4)
//              Wi [2720, 2720+4352)  Wj [+4352]   rows padded to 17 units (c*17+e4)
//   phase 2:   Uc [0,2624)  Vc [2624,5248)  tab [5248,5992)   (overlay)
//
// Phase-1 lane map: lane = fg*8 + cl, c = warp*8 + cl, f in {fg, fg+4, ... fg+36}.
// 17-unit padding makes W loads 1 wavefront (8 rows x 4-way bcast, bank-disjoint)
// and xs loads 1 wavefront (4 rows x 8-way bcast) -> 12 wf per e4/warp vs 18.
//
// Phase 2: row-pairing (p0(c)=27c mod 32 == p0(c+32)); 22-entry tab window cached
// in registers per pair; 3 L1 wavefronts per 32 outputs (u, v, store).

#define FN 39
#define EN 64
#define CN 64
#define PN 741            // 39*38/2
#define OUTB (CN * PN)    // 47424 floats per batch
#define THREADS 256

#define XS_OFF  0                     // 680 float4 = 2720 floats
#define W_OFF   2720                  // Wi: 1088 float4, Wj: 1088 float4
#define UC_OFF  0
#define VC_OFF  2624
#define TAB_OFF 5248
#define SMEM_FLOATS 11424
#define SMEM_BYTES  (SMEM_FLOATS * 4) // 45696

// packed fp32x2 FMA (Blackwell; exact fp32 semantics, 2x FFMA throughput)
#define FMA_F32X2(acc, a, b) \
    asm("fma.rn.f32x2 %0, %1, %2, %0;" : "+l"(acc) : "l"(a), "l"(b))

extern __shared__ float smem[];

__global__ void __launch_bounds__(THREADS, 4)
interconv_kernel(const float* __restrict__ x,
                 const float* __restrict__ W,
                 const float* __restrict__ bias,
                 float* __restrict__ out)
{
    const int tid = threadIdx.x;
    const long long b = blockIdx.x;

    // ---- Phase 0: stage x and W (float4, 17-unit row padding) -----------
    {
        float4* xs4 = (float4*)(smem + XS_OFF);
        const float4* xb4 = (const float4*)(x + b * (long long)(FN * EN));
        #pragma unroll
        for (int it = 0; it < 3; it++) {
            int idx = tid + it * THREADS;
            if (idx < (FN * EN) / 4)
                xs4[idx + (idx >> 4)] = xb4[idx];   // f*17 + e4
        }
        if (tid < EN) {                             // zero pad row f=39
            int e4 = tid >> 2, r = tid & 3;
            smem[XS_OFF + (39 * 17 + e4) * 4 + r] = 0.f;
        }

        // W gmem: [c][128] floats (k=0 -> Wi, k=1 -> Wj); smem stride 17 units
        float4* Wi4 = (float4*)(smem + W_OFF);
        float4* Wj4 = Wi4 + 1088;
        const float4* Wg4 = (const float4*)W;
        #pragma unroll
        for (int it = 0; it < 8; it++) {
            int idx = tid + it * THREADS;           // 2048 float4 total
            int c = idx >> 5, q = idx & 31;
            float4 w = Wg4[idx];
            if (q < 16) Wi4[c * 17 + q] = w;
            else        Wj4[c * 17 + (q - 16)] = w;
        }
    }
    __syncthreads();

    // ---- Phase 1: U = x @ Wi^T + b, V = x @ Wj^T  (f32x2, remapped) -----
    const int lane = tid & 31;
    const int wrp  = tid >> 5;
    const int cl = lane & 7;          // c within warp's octet
    const int fg = lane >> 3;         // 0..3
    const int c  = wrp * 8 + cl;      // this thread's c

    unsigned long long au[10], av[10];
    #pragma unroll
    for (int k = 0; k < 10; k++) { au[k] = 0ull; av[k] = 0ull; }

    {
        const ulonglong2* xs2 = (const ulonglong2*)(smem + XS_OFF);   // [f*17+e4]
        const ulonglong2* Wi2 = (const ulonglong2*)(smem + W_OFF);    // [c*17+e4]
        const ulonglong2* Wj2 = Wi2 + 1088;

        #pragma unroll
        for (int e4 = 0; e4 < 16; e4++) {
            ulonglong2 wi = Wi2[c * 17 + e4];
            ulonglong2 wj = Wj2[c * 17 + e4];
            #pragma unroll
            for (int k = 0; k < 10; k++) {
                ulonglong2 xv = xs2[(fg + 4 * k) * 17 + e4];  // f=39 row is zeros
                FMA_F32X2(au[k], xv.x, wi.x);
                FMA_F32X2(au[k], xv.y, wi.y);
                FMA_F32X2(av[k], xv.x, wj.x);
                FMA_F32X2(av[k], xv.y, wj.y);
            }
        }
    }
    __syncthreads();   // all xs/W reads done; safe to overlay

    // ---- Phase 1b: write Uc/Vc (transposed, stride 41) + build tab ------
    float* Uc = smem + UC_OFF;                // [c][41]
    float* Vc = smem + VC_OFF;                // [c][41]
    unsigned* tab = (unsigned*)(smem + TAB_OFF);

    {
        const float bc = __ldg(bias + c);
        #pragma unroll
        for (int k = 0; k < 10; k++) {
            int f = fg + 4 * k;               // f<=39; f=39 lands in row pad
            float ulo = __uint_as_float((unsigned)au[k]);
            float uhi = __uint_as_float((unsigned)(au[k] >> 32));
            float vlo = __uint_as_float((unsigned)av[k]);
            float vhi = __uint_as_float((unsigned)(av[k] >> 32));
            Uc[c * 41 + f] = ulo + uhi + bc;  // bias folded into U
            Vc[c * 41 + f] = vlo + vhi;
        }
        // pair table: np.triu_indices(F,1) row-major; byte offsets (i*4 | j*4<<16)
        for (int p = tid; p < PN; p += THREADS) {
            int i = 0, rem = p;
            while (rem >= FN - 1 - i) { rem -= FN - 1 - i; i++; }
            int j = i + 1 + rem;
            tab[p] = (unsigned)(i * 4) | ((unsigned)(j * 4) << 16);
        }
    }
    __syncthreads();

    // ---- Phase 2: expansion + relu, paired rows, register-cached tab -----
    float* outb = out + b * (long long)OUTB;

    #pragma unroll 1
    for (int k = 0; k < 4; k++) {
        const int r  = wrp * 4 + k;           // rows r and r+32 share p0
        const int p0 = (27 * r) & 31;

        // preload the 22-entry aligned tab window into registers
        unsigned tw[22];
        {
            const unsigned* tb = tab + p0 + lane;
            #pragma unroll
            for (int it = 0; it < 22; it++) tw[it] = tb[it * 32];
        }

        #pragma unroll
        for (int h = 0; h < 2; h++) {
            const int gc = r + 32 * h;
            const char* bu = (const char*)(Uc + gc * 41);
            const char* bv = (const char*)(Vc + gc * 41);
            float* po = outb + gc * PN;

            // head: p in [0, p0)
            if (lane < p0) {
                unsigned t = tab[lane];
                float u = *(const float*)(bu + (t & 0xFFFFu));
                float v = *(const float*)(bv + (t >> 16));
                __stcs(po + lane, fmaxf(u + v, 0.f));
            }

            // main: 22 full warp-iterations, register tab, 128B-aligned stores
            float* po2 = po + p0;
            #pragma unroll
            for (int it = 0; it < 22; it++) {
                unsigned t = tw[it];
                float u = *(const float*)(bu + (t & 0xFFFFu));
                float v = *(const float*)(bv + (t >> 16));
                __stcs(po2 + it * 32 + lane, fmaxf(u + v, 0.f));
            }

            // tail: p in [p0+704, 741)
            int p = p0 + 704 + lane;
            if (p < PN) {
                unsigned t = tab[p];
                float u = *(const float*)(bu + (t & 0xFFFFu));
                float v = *(const float*)(bv + (t >> 16));
                __stcs(po + p, fmaxf(u + v, 0.f));
            }
            p += 32;
            if (p < PN) {
                unsigned t = tab[p];
                float u = *(const float*)(bu + (t & 0xFFFFu));
                float v = *(const float*)(bv + (t >> 16));
                __stcs(po + p, fmaxf(u + v, 0.f));
            }
        }
    }
}

extern "C" void kernel_launch(void* const* d_in, const int* in_sizes, int n_in,
                              void* d_out, int out_size)
{
    const float* x    = (const float*)d_in[0];
    const float* W    = (const float*)d_in[1];
    const float* bias = (const float*)d_in[2];
    float* out = (float*)d_out;

    const int B = in_sizes[0] / (FN * EN);   // 2048

    cudaFuncSetAttribute(interconv_kernel,
                         cudaFuncAttributeMaxDynamicSharedMemorySize, SMEM_BYTES);
    interconv_kernel<<<B, THREADS, SMEM_BYTES>>>(x, W, bias, out);
}